// round 12
// baseline (speedup 1.0000x reference)
#include <cuda_runtime.h>
#include <cuda_bf16.h>
#include <cstdint>
#include <cstring>
#include <math.h>

#define NN 100000
#define NE 1600000
#define NF 500
#define NH 128
#define NC 40
#define SCAN_B 512
#define NBLK ((NN + SCAN_B - 1) / SCAN_B)   // 196

// ---------------- static device scratch (no allocs allowed) ----------------
__device__ float g_S[NN * NH];     // support = h @ W
__device__ float g_H[NN * NH];     // hidden ping
__device__ float g_H2[NN * NH];    // hidden pong
__device__ float g_A4[NN * NC];    // layer-4 aggregate (pre log_softmax)
__device__ __nv_bfloat16 g_Wh[4][512 * 128];  // weights, hi part, [k][n], zero-padded rows
__device__ __nv_bfloat16 g_Wl[4][512 * 128];  // weights, lo part
__device__ int   g_deg[NN];
__device__ int   g_cur[NN];
__device__ int   g_rp[NN + 1];     // CSR row pointers
__device__ int   g_cs[NE];         // CSR col (source node) per edge
__device__ float g_ws[NE];         // CSR edge weight
__device__ int   g_bsum[NBLK];

// ---------------- CSR construction ----------------
__global__ void k_zero() {
    int i = blockIdx.x * blockDim.x + threadIdx.x;
    if (i < NN) { g_deg[i] = 0; g_cur[i] = 0; }
}
__global__ void k_count(const int* __restrict__ row) {
    int e = blockIdx.x * blockDim.x + threadIdx.x;
    if (e < NE) atomicAdd(&g_deg[row[e]], 1);
}
__global__ void k_scan1() {
    __shared__ int s[SCAN_B];
    int i = blockIdx.x * SCAN_B + threadIdx.x;
    int v = (i < NN) ? g_deg[i] : 0;
    s[threadIdx.x] = v;
    __syncthreads();
    for (int off = 1; off < SCAN_B; off <<= 1) {
        int t = (threadIdx.x >= off) ? s[threadIdx.x - off] : 0;
        __syncthreads();
        s[threadIdx.x] += t;
        __syncthreads();
    }
    if (i < NN) g_rp[i] = s[threadIdx.x];
    if (threadIdx.x == SCAN_B - 1) g_bsum[blockIdx.x] = s[SCAN_B - 1];
}
__global__ void k_scan2() {
    __shared__ int s[256];
    int v = (threadIdx.x < NBLK) ? g_bsum[threadIdx.x] : 0;
    s[threadIdx.x] = v;
    __syncthreads();
    for (int off = 1; off < 256; off <<= 1) {
        int t = (threadIdx.x >= off) ? s[threadIdx.x - off] : 0;
        __syncthreads();
        s[threadIdx.x] += t;
        __syncthreads();
    }
    if (threadIdx.x < NBLK) g_bsum[threadIdx.x] = s[threadIdx.x] - v;
}
__global__ void k_scan3() {
    int i = blockIdx.x * SCAN_B + threadIdx.x;
    if (i < NN) g_rp[i] = g_rp[i] - g_deg[i] + g_bsum[blockIdx.x];
    if (i == 0) g_rp[NN] = NE;
}
__global__ void k_scatter(const int* __restrict__ row, const int* __restrict__ col,
                          const float* __restrict__ w) {
    int e = blockIdx.x * blockDim.x + threadIdx.x;
    if (e < NE) {
        int r = row[e];
        int pos = g_rp[r] + atomicAdd(&g_cur[r], 1);
        g_cs[pos] = col[e];
        g_ws[pos] = w[e];
    }
}

// ---------------- weight split prep: W[K][Nw] -> Wh/Wl [512][128] bf16 ----------------
// Nw=128 for W1..W3; W4 (Nw=40) is zero-padded to 128 cols here as well.
__global__ void k_splitW(const float* __restrict__ W, int K, int Nw,
                         __nv_bfloat16* __restrict__ Wh, __nv_bfloat16* __restrict__ Wl) {
    int i = blockIdx.x * blockDim.x + threadIdx.x;   // 512*128
    if (i >= 512 * 128) return;
    int k = i >> 7, n = i & 127;
    float v = (k < K && n < Nw) ? W[k * Nw + n] : 0.f;
    __nv_bfloat16 h = __float2bfloat16(v);
    Wh[i] = h;
    Wl[i] = __float2bfloat16(v - __bfloat162float(h));
}

// ---------------- bf16-split tensor-core GEMM (mma.sync, cp.async fill) ----------------
// C[M,128] = A[M,K] @ W[K,128], A fp32, W pre-split bf16 (Wh/Wl, [k][n] 512x128).
// acc += Ah*Bh + Ah*Bl + Al*Bh  (~2^-17 effective precision).
// CTA: 128x128 tile, BK=32, 256 threads = 8 warps (4m x 2n), warp tile 32x64.
// 2 CTAs/SM (launch_bounds 256,2): fill via cp.async (no prefetch registers),
// fp32 A staged in smem, converted smem->smem to split-bf16 tiles.
#define LDT 40           // A bf16 tile row elems (80 B, 16B-multiple, conflict-free)
#define LDB 136          // B bf16 tile row elems (272 B)
#define FPA_STRIDE 144   // fp32 staging row bytes (128 data + 16 pad)
#define OFF_FPA 0
#define OFF_AH  18432                    // 128*144
#define OFF_AL  (OFF_AH + 128 * LDT * 2) // +10240
#define OFF_BH  (OFF_AL + 128 * LDT * 2) // +10240
#define OFF_BL  (OFF_BH + 32 * LDB * 2)  // +8704
#define GEMM_STAGE (OFF_BL + 32 * LDB * 2)   // 56320
#define GEMM_SMEM  (2 * GEMM_STAGE)          // 112640

__device__ __forceinline__ uint32_t smem_u32(const void* p) {
    uint32_t a;
    asm("{ .reg .u64 t; cvta.to.shared.u64 t, %1; cvt.u32.u64 %0, t; }" : "=r"(a) : "l"(p));
    return a;
}
#define CP_ASYNC16(smem, gptr, sz) \
    asm volatile("cp.async.cg.shared.global [%0], [%1], 16, %2;" \
                 :: "r"(smem), "l"(gptr), "r"(sz))
#define CP_COMMIT() asm volatile("cp.async.commit_group;")
#define CP_WAIT1()  asm volatile("cp.async.wait_group 1;")
#define CP_WAIT0()  asm volatile("cp.async.wait_group 0;")
#define LDMX4(r0, r1, r2, r3, a) \
    asm volatile("ldmatrix.sync.aligned.m8n8.x4.shared.b16 {%0,%1,%2,%3}, [%4];" \
                 : "=r"(r0), "=r"(r1), "=r"(r2), "=r"(r3) : "r"(a))
#define LDMX4T(r0, r1, r2, r3, a) \
    asm volatile("ldmatrix.sync.aligned.m8n8.x4.trans.shared.b16 {%0,%1,%2,%3}, [%4];" \
                 : "=r"(r0), "=r"(r1), "=r"(r2), "=r"(r3) : "r"(a))
#define MMA16816(d, a, b0v, b1v) \
    asm volatile("mma.sync.aligned.m16n8k16.row.col.f32.bf16.bf16.f32 " \
                 "{%0,%1,%2,%3}, {%4,%5,%6,%7}, {%8,%9}, {%0,%1,%2,%3};" \
                 : "+f"((d)[0]), "+f"((d)[1]), "+f"((d)[2]), "+f"((d)[3]) \
                 : "r"((a)[0]), "r"((a)[1]), "r"((a)[2]), "r"((a)[3]), \
                   "r"(b0v), "r"(b1v))

__global__ __launch_bounds__(256, 2) void k_gemm_mma(const float* __restrict__ A,
                                                     const __nv_bfloat16* __restrict__ Wh,
                                                     const __nv_bfloat16* __restrict__ Wl,
                                                     float* __restrict__ C,
                                                     int M, int K) {
    extern __shared__ __align__(16) uint8_t smem[];

    const int tid  = threadIdx.x;
    const int wid  = tid >> 5, lane = tid & 31;
    const int m0   = blockIdx.x * 128;
    const int wm   = (wid & 3) * 32;    // warp row base
    const int wn   = (wid >> 2) * 64;   // warp col base

    const int lr  = lane & 7;
    const int grp = lane >> 3;
    const int aRow = (grp & 1) * 8 + lr;   // A: m offset
    const int aCol = (grp >> 1) * 8;       // A: k offset
    const int bK   = (grp & 1) * 8 + lr;   // B: k row (trans)
    const int bN   = (grp >> 1) * 8;       // B: n offset

    const uint32_t uS0 = smem_u32(smem);

    float acc[2][8][4];
#pragma unroll
    for (int i = 0; i < 2; i++)
#pragma unroll
        for (int j = 0; j < 8; j++)
#pragma unroll
            for (int q = 0; q < 4; q++) acc[i][j][q] = 0.f;

    const int nchunk = (K + 31) / 32;

    // -------- cp.async issue for one chunk (A fp32 staging + B split tiles) --------
    auto issue = [&](int c, int stage) {
        const uint32_t sb = uS0 + (uint32_t)stage * GEMM_STAGE;
        const int k0 = c * 32;
        // A: 128 rows x 8 x 16B  -> 4 ops/thread
#pragma unroll
        for (int j = 0; j < 4; j++) {
            int id = tid * 4 + j;
            int r  = id >> 3, ch = id & 7;
            int m  = m0 + r, k = k0 + ch * 4;
            int sz = (m < M && k < K) ? 16 : 0;
            int mc = (m < M) ? m : (M - 1);   // keep address in-bounds even when sz=0
            int kc = (k < K) ? k : 0;
            const float* src = A + (size_t)mc * K + kc;
            CP_ASYNC16(sb + OFF_FPA + r * FPA_STRIDE + ch * 16, src, sz);
        }
        // B: 2 halves x 32 rows x 16 x 16B -> 4 ops/thread (W arrays pre-padded to 512 rows)
#pragma unroll
        for (int j = 0; j < 4; j++) {
            int id   = tid * 4 + j;
            int half = id >> 9;
            int r    = (id >> 4) & 31;
            int ch   = id & 15;
            const __nv_bfloat16* W = half ? Wl : Wh;
            const __nv_bfloat16* src = W + (size_t)(k0 + r) * 128 + ch * 8;
            uint32_t off = (half ? OFF_BL : OFF_BH) + r * (LDB * 2) + ch * 16;
            CP_ASYNC16(sb + off, src, 16);
        }
        CP_COMMIT();
    };

    // -------- smem fp32 -> split-bf16 conversion for one chunk --------
    auto convert = [&](int stage) {
        const uint32_t sb = uS0 + (uint32_t)stage * GEMM_STAGE;
        int r = tid >> 1, h = tid & 1;
        const uint32_t fp = sb + OFF_FPA + r * FPA_STRIDE + h * 64;
        const uint32_t oh = sb + OFF_AH + r * (LDT * 2) + h * 32;
        const uint32_t ol = sb + OFF_AL + r * (LDT * 2) + h * 32;
#pragma unroll
        for (int i = 0; i < 4; i++) {
            float vx, vy, vz, vw;
            asm volatile("ld.shared.v4.f32 {%0,%1,%2,%3}, [%4];"
                         : "=f"(vx), "=f"(vy), "=f"(vz), "=f"(vw) : "r"(fp + i * 16));
            __nv_bfloat162 h01 = __floats2bfloat162_rn(vx, vy);
            __nv_bfloat162 h23 = __floats2bfloat162_rn(vz, vw);
            __nv_bfloat162 l01 = __floats2bfloat162_rn(vx - __bfloat162float(h01.x),
                                                       vy - __bfloat162float(h01.y));
            __nv_bfloat162 l23 = __floats2bfloat162_rn(vz - __bfloat162float(h23.x),
                                                       vw - __bfloat162float(h23.y));
            uint32_t uh01, uh23, ul01, ul23;
            memcpy(&uh01, &h01, 4); memcpy(&uh23, &h23, 4);
            memcpy(&ul01, &l01, 4); memcpy(&ul23, &l23, 4);
            asm volatile("st.shared.v2.b32 [%0], {%1,%2};" :: "r"(oh + i * 8), "r"(uh01), "r"(uh23));
            asm volatile("st.shared.v2.b32 [%0], {%1,%2};" :: "r"(ol + i * 8), "r"(ul01), "r"(ul23));
        }
    };

    // -------- pipeline --------
    issue(0, 0);
    for (int c = 0; c < nchunk; c++) {
        const int  st      = c & 1;
        const bool hasNext = (c + 1 < nchunk);
        if (hasNext) { issue(c + 1, st ^ 1); CP_WAIT1(); } else { CP_WAIT0(); }
        __syncthreads();
        convert(st);
        __syncthreads();

        const uint32_t sb  = uS0 + (uint32_t)st * GEMM_STAGE;
        const uint32_t uAh = sb + OFF_AH;
        const uint32_t uAl = sb + OFF_AL;
        const uint32_t uBh = sb + OFF_BH;
        const uint32_t uBl = sb + OFF_BL;

#pragma unroll
        for (int ks = 0; ks < 2; ks++) {
            const int kb = ks * 16;
            uint32_t ah[2][4], al[2][4];
#pragma unroll
            for (int mt = 0; mt < 2; mt++) {
                uint32_t off = (uint32_t)((wm + mt * 16 + aRow) * (LDT * 2) + (kb + aCol) * 2);
                LDMX4(ah[mt][0], ah[mt][1], ah[mt][2], ah[mt][3], uAh + off);
                LDMX4(al[mt][0], al[mt][1], al[mt][2], al[mt][3], uAl + off);
            }
#pragma unroll
            for (int p = 0; p < 4; p++) {
                uint32_t off = (uint32_t)((kb + bK) * (LDB * 2) + (wn + p * 16 + bN) * 2);
                uint32_t bh0, bh1, bh2, bh3, bl0, bl1, bl2, bl3;
                LDMX4T(bh0, bh1, bh2, bh3, uBh + off);
                LDMX4T(bl0, bl1, bl2, bl3, uBl + off);
#pragma unroll
                for (int mt = 0; mt < 2; mt++) {
                    MMA16816(acc[mt][2 * p],     ah[mt], bh0, bh1);
                    MMA16816(acc[mt][2 * p + 1], ah[mt], bh2, bh3);
                    MMA16816(acc[mt][2 * p],     ah[mt], bl0, bl1);
                    MMA16816(acc[mt][2 * p + 1], ah[mt], bl2, bl3);
                    MMA16816(acc[mt][2 * p],     al[mt], bh0, bh1);
                    MMA16816(acc[mt][2 * p + 1], al[mt], bh2, bh3);
                }
            }
        }
        __syncthreads();   // stage reusable for next issue
    }

    // ---- epilogue
    const int fr = lane >> 2, fc = (lane & 3) * 2;
#pragma unroll
    for (int mt = 0; mt < 2; mt++) {
        int r0 = m0 + wm + mt * 16 + fr;
#pragma unroll
        for (int nt = 0; nt < 8; nt++) {
            int cbase = wn + nt * 8 + fc;
            if (r0 < M)
                *(float2*)(C + (size_t)r0 * 128 + cbase) =
                    make_float2(acc[mt][nt][0], acc[mt][nt][1]);
            if (r0 + 8 < M)
                *(float2*)(C + (size_t)(r0 + 8) * 128 + cbase) =
                    make_float2(acc[mt][nt][2], acc[mt][nt][3]);
        }
    }
}

// ---------------- CSR SpMM + bias (+relu) ----------------
__global__ __launch_bounds__(256) void k_spmm(const float* __restrict__ S,
                                              float* __restrict__ H,
                                              const float* __restrict__ bias,
                                              int F, int FsQ, int do_relu) {
    int wid  = (blockIdx.x * 256 + threadIdx.x) >> 5;
    if (wid >= NN) return;
    int lane = threadIdx.x & 31;
    int f    = lane * 4;
    if (f >= F) return;
    int fq = f >> 2, Fq = F >> 2;

    int beg = g_rp[wid], end = g_rp[wid + 1];
    const float4* Sv = (const float4*)S;
    float4 acc = make_float4(0.f, 0.f, 0.f, 0.f);
#pragma unroll 4
    for (int e = beg; e < end; e++) {
        int   c = g_cs[e];
        float w = g_ws[e];
        float4 v = Sv[(size_t)c * FsQ + fq];
        acc.x += w * v.x; acc.y += w * v.y; acc.z += w * v.z; acc.w += w * v.w;
    }
    float4 b = ((const float4*)bias)[fq];
    acc.x += b.x; acc.y += b.y; acc.z += b.z; acc.w += b.w;
    if (do_relu) {
        acc.x = fmaxf(acc.x, 0.f); acc.y = fmaxf(acc.y, 0.f);
        acc.z = fmaxf(acc.z, 0.f); acc.w = fmaxf(acc.w, 0.f);
    }
    ((float4*)H)[(size_t)wid * Fq + fq] = acc;
}

// ---------------- log_softmax over 40 classes ----------------
__global__ __launch_bounds__(256) void k_lsm(float* __restrict__ out) {
    int wid = (blockIdx.x * 256 + threadIdx.x) >> 5;
    if (wid >= NN) return;
    int lane = threadIdx.x & 31;
    const float* a = g_A4 + (size_t)wid * NC;
    float v0 = a[lane];
    float v1 = (lane + 32 < NC) ? a[lane + 32] : -1e30f;
    float m = fmaxf(v0, v1);
#pragma unroll
    for (int o = 16; o; o >>= 1) m = fmaxf(m, __shfl_xor_sync(0xffffffffu, m, o));
    float s = expf(v0 - m) + ((lane + 32 < NC) ? expf(v1 - m) : 0.f);
#pragma unroll
    for (int o = 16; o; o >>= 1) s += __shfl_xor_sync(0xffffffffu, s, o);
    float l = m + logf(s);
    out[(size_t)wid * NC + lane] = v0 - l;
    if (lane + 32 < NC) out[(size_t)wid * NC + lane + 32] = v1 - l;
}

// ---------------- launch ----------------
extern "C" void kernel_launch(void* const* d_in, const int* in_sizes, int n_in,
                              void* d_out, int out_size) {
    const float* x  = (const float*)d_in[0];
    const int*   row = (const int*)d_in[1];
    const int*   col = (const int*)d_in[2];
    const float* ew  = (const float*)d_in[3];
    const float* W1 = (const float*)d_in[4];  const float* b1 = (const float*)d_in[5];
    const float* W2 = (const float*)d_in[6];  const float* b2 = (const float*)d_in[7];
    const float* W3 = (const float*)d_in[8];  const float* b3 = (const float*)d_in[9];
    const float* W4 = (const float*)d_in[10]; const float* b4 = (const float*)d_in[11];
    float* out = (float*)d_out;

    void *pS, *pH, *pH2, *pA4, *pWh, *pWl;
    cudaGetSymbolAddress(&pS,  g_S);
    cudaGetSymbolAddress(&pH,  g_H);
    cudaGetSymbolAddress(&pH2, g_H2);
    cudaGetSymbolAddress(&pA4, g_A4);
    cudaGetSymbolAddress(&pWh, g_Wh);
    cudaGetSymbolAddress(&pWl, g_Wl);
    float* S  = (float*)pS;
    float* H  = (float*)pH;
    float* H2 = (float*)pH2;
    float* A4 = (float*)pA4;
    __nv_bfloat16* Wh = (__nv_bfloat16*)pWh;   // [4][512*128]
    __nv_bfloat16* Wl = (__nv_bfloat16*)pWl;

    cudaFuncSetAttribute(k_gemm_mma, cudaFuncAttributeMaxDynamicSharedMemorySize, GEMM_SMEM);

    const int EB = (NE + 255) / 256;
    const int GM = (NN + 127) / 128;     // 782 row tiles
    const int SB = (NN + 7) / 8;         // warp-per-row
    const int WB = (512 * 128 + 255) / 256;

    // launch order keeps gemm1 at index 3 (0-based) for the ncu capture window
    k_zero<<<(NN + 255) / 256, 256>>>();
    k_count<<<EB, 256>>>(row);
    k_splitW<<<WB, 256>>>(W1, NF, NH, Wh + 0 * 65536, Wl + 0 * 65536);
    k_gemm_mma<<<GM, 256, GEMM_SMEM>>>(x, Wh + 0 * 65536, Wl + 0 * 65536, S, NN, NF);
    k_scan1<<<NBLK, SCAN_B>>>();
    k_scan2<<<1, 256>>>();
    k_scan3<<<NBLK, SCAN_B>>>();
    k_scatter<<<EB, 256>>>(row, col, ew);
    k_splitW<<<WB, 256>>>(W2, NH, NH, Wh + 1 * 65536, Wl + 1 * 65536);
    k_splitW<<<WB, 256>>>(W3, NH, NH, Wh + 2 * 65536, Wl + 2 * 65536);
    k_splitW<<<WB, 256>>>(W4, NH, NC, Wh + 3 * 65536, Wl + 3 * 65536);

    // layer 1 aggregate
    k_spmm<<<SB, 256>>>(S, H, b1, NH, NH / 4, 1);
    // layer 2
    k_gemm_mma<<<GM, 256, GEMM_SMEM>>>(H, Wh + 1 * 65536, Wl + 1 * 65536, S, NN, NH);
    k_spmm<<<SB, 256>>>(S, H2, b2, NH, NH / 4, 1);
    // layer 3
    k_gemm_mma<<<GM, 256, GEMM_SMEM>>>(H2, Wh + 2 * 65536, Wl + 2 * 65536, S, NN, NH);
    k_spmm<<<SB, 256>>>(S, H, b3, NH, NH / 4, 1);
    // layer 4 (W4 zero-padded to 128 cols in split prep) + log_softmax
    k_gemm_mma<<<GM, 256, GEMM_SMEM>>>(H, Wh + 3 * 65536, Wl + 3 * 65536, S, NN, NH);
    k_spmm<<<SB, 256>>>(S, A4, b4, NC, 128 / 4, 0);
    k_lsm<<<SB, 256>>>(out);
}